// round 14
// baseline (speedup 1.0000x reference)
#include <cuda_runtime.h>
#include <cuda_fp16.h>
#include <cstdint>

// Problem constants
#define BB 128      // batch
#define TT 256      // timesteps
#define DD 256      // embed dim
#define HH 1024     // hidden
#define CC 10       // classes
#define VV 3        // vocab
#define GRID 128    // persistent CTAs (1 per 8 h-cols)
#define NTHREADS 256
#define KS16 64     // 1024 / 16 (K per m16n8k16 mma)

// SMEM: Bf uint4[2][64][32] = 64KB weight fragments (fp16), then xzsm[3][33]
#define SMEM_BF_BYTES (2 * 64 * 32 * 16)
#define SMEM_XZ_OFF   SMEM_BF_BYTES
#define SMEM_TOTAL    (SMEM_XZ_OFF + 3 * 33 * 4)

// h in A-fragment order, fp16 (R2-R4 proven layout):
// g_hfrag[buf][s][rg][lane], lane=(r4=lane/4, q=lane%4):
//   .x = half2(h[16rg+r4][8s+2q],   h[16rg+r4][8s+2q+1])
//   .y = half2(h[16rg+8+r4][8s+2q], h[16rg+8+r4][8s+2q+1])
// slice s = h-cols [8s, 8s+8), owned by CTA s.
__device__ uint2 g_hfrag[2][128][8][32];
__device__ float g_xz3[VV * 4 * HH];   // per-token x-side projection [v][gate*1024+j]
__device__ int   g_xidx[TT * BB];      // token index, time-major
__device__ int   g_x64;
// Per-CTA data-flow flags (R4 scheme, unchanged). g_flag[ng] = s means CTA ng
// has PUBLISHED h(s-1) (finished step s-2), hence also finished READING h(s-2).
// Consumer of step t needs flag >= t+1 per producer before consuming h(t).
// WAR safety: writer of h(t+1) (same buffer as h(t-1)) has seen all flags
// >= t+1, which implies every CTA finished reading h(t-1).
__device__ unsigned g_flag[GRID];

// ---------------------------------------------------------------------------
__device__ __forceinline__ unsigned packh2(float a, float b) {
    __half2 h = __floats2half2_rn(a, b);
    return *(unsigned*)&h;
}

__device__ __forceinline__ uint2 ldcg2(const uint2* p) {
    uint2 r;
    asm volatile("ld.global.cg.v2.u32 {%0,%1},[%2];" : "=r"(r.x), "=r"(r.y) : "l"(p));
    return r;
}

__device__ __forceinline__ void mma_f16(float* c, unsigned a0, unsigned a1,
                                        unsigned a2, unsigned a3,
                                        unsigned b0, unsigned b1) {
    asm volatile(
        "mma.sync.aligned.m16n8k16.row.col.f32.f16.f16.f32 "
        "{%0,%1,%2,%3}, {%4,%5,%6,%7}, {%8,%9}, {%0,%1,%2,%3};"
        : "+f"(c[0]), "+f"(c[1]), "+f"(c[2]), "+f"(c[3])
        : "r"(a0), "r"(a1), "r"(a2), "r"(a3), "r"(b0), "r"(b1));
}

__device__ __forceinline__ float tanha(float x) {
    float y;
    asm("tanh.approx.f32 %0,%1;" : "=f"(y) : "f"(x));
    return y;
}

__device__ __forceinline__ float sigmf(float x) {
    float e = __expf(-x);
    float r;
    asm("rcp.approx.f32 %0,%1;" : "=f"(r) : "f"(1.0f + e));
    return r;
}

__device__ __forceinline__ float lstm_elem(float zg, float zi, float zf, float zo, float& c) {
    float gg = tanha(zg);
    float ii = sigmf(zi);
    float ff = sigmf(zf);
    float oo = sigmf(zo);
    c = c * ff + gg * ii;
    return tanha(c) * oo;
}

// Warp-collective: wait until producers [32g, 32g+32) have flag >= tgt.
__device__ __forceinline__ void wait_group(int g, unsigned tgt) {
    const unsigned* f = &g_flag[g * 32 + (threadIdx.x & 31)];
    unsigned v;
    do {
        asm volatile("ld.acquire.gpu.global.u32 %0,[%1];" : "=r"(v) : "l"(f) : "memory");
    } while (__any_sync(0xffffffffu, v < tgt));
}

__device__ __forceinline__ void publish(int ng, unsigned val) {
    asm volatile("st.release.gpu.global.u32 [%0],%1;"
                 :: "l"(&g_flag[ng]), "r"(val) : "memory");
}

// ---------------------------------------------------------------------------
__global__ void k_init() {
    int tid = threadIdx.x;
    if (tid < GRID) g_flag[tid] = 0u;
}

// Detect x dtype without reading past an int32-sized allocation.
__global__ void k_detect(const unsigned* __restrict__ xw) {
    __shared__ int flag;
    if (threadIdx.x == 0) flag = 0;
    __syncthreads();
    for (int i = threadIdx.x; i < 2048; i += blockDim.x)
        if (xw[2 * i + 1] != 0u) flag = 1;
    __syncthreads();
    if (threadIdx.x == 0) g_x64 = (flag == 0) ? 1 : 0;
}

__global__ void k_idx(const void* __restrict__ x) {
    int b = blockIdx.x;
    int t = threadIdx.x;
    long long v;
    if (g_x64) v = ((const long long*)x)[(size_t)b * TT + t];
    else       v = ((const int*)x)[(size_t)b * TT + t];
    g_xidx[t * BB + b] = (int)v;
}

__global__ void k_xz3(const float* __restrict__ emb,
                      const float* __restrict__ W_gx, const float* __restrict__ W_ix,
                      const float* __restrict__ W_fx, const float* __restrict__ W_ox,
                      const float* __restrict__ b_g, const float* __restrict__ b_i,
                      const float* __restrict__ b_f, const float* __restrict__ b_o) {
    int gid = blockIdx.x * blockDim.x + threadIdx.x;
    if (gid >= VV * 4 * HH) return;
    int v = gid >> 12;
    int col = gid & 4095;
    int gate = col >> 10;
    int j = col & 1023;
    const float* W = (gate == 0) ? W_gx : (gate == 1) ? W_ix : (gate == 2) ? W_fx : W_ox;
    const float* bb = (gate == 0) ? b_g : (gate == 1) ? b_i : (gate == 2) ? b_f : b_o;
    float s = bb[j];
    const float* ev = emb + v * DD;
#pragma unroll 8
    for (int d = 0; d < DD; ++d) s += ev[d] * W[d * HH + j];
    g_xz3[gid] = s;
}

// ---------------------------------------------------------------------------
// Persistent recurrent kernel (R4 verbatim + per-CTA staggered group order).
// CTA ng owns h-cols [8ng, 8ng+8). Warp wg: batch rows [16wg, 16wg+16),
// all 32 z-cols (ntile = gate). c-state in registers.
// Stagger: CTA ng consumes groups (ng+gi)&3 -- at any instant the chip's
// A-loads spread over all four quarters of h instead of bursting on one.
__global__ void __launch_bounds__(NTHREADS, 1)
lstm_persistent(const float* __restrict__ W_gh, const float* __restrict__ W_ih,
                const float* __restrict__ W_fh, const float* __restrict__ W_oh) {
    extern __shared__ __align__(16) char smem[];
    uint4* Bf = (uint4*)smem;                     // [2][64][32]
    float* xzsm = (float*)(smem + SMEM_XZ_OFF);   // [3][33]

    const int ng = blockIdx.x;
    const int tid = threadIdx.x;
    const int wg = tid >> 5;
    const int lane = tid & 31;
    const int q = lane & 3;
    const int r4 = lane >> 2;
    const int R = 16 * wg + r4;

    // ---- One-time: weight slice -> fp16 B-fragments in SMEM ----
    for (int i = tid; i < 2 * KS16 * 32; i += NTHREADS) {
        int t = i & 31;
        int ks = (i >> 5) & 63;
        int p = i >> 11;                      // 0: gates g,i  1: gates f,o
        int col = ng * 8 + (t >> 2);
        int k0 = 16 * ks + 2 * (t & 3);
        const float* WA = p ? W_fh : W_gh;
        const float* WB = p ? W_oh : W_ih;
        uint4 v;
        v.x = packh2(WA[(size_t)k0 * HH + col],       WA[(size_t)(k0 + 1) * HH + col]);
        v.y = packh2(WA[(size_t)(k0 + 8) * HH + col], WA[(size_t)(k0 + 9) * HH + col]);
        v.z = packh2(WB[(size_t)k0 * HH + col],       WB[(size_t)(k0 + 1) * HH + col]);
        v.w = packh2(WB[(size_t)(k0 + 8) * HH + col], WB[(size_t)(k0 + 9) * HH + col]);
        Bf[i] = v;
    }

    // xz slice: xzsm[v][gate*8 + j] for this CTA's 8 cols
    for (int i = tid; i < VV * 32; i += NTHREADS) {
        int v = i >> 5;
        int lc = i & 31;
        xzsm[v * 33 + lc] = g_xz3[v * 4096 + (lc >> 3) * HH + ng * 8 + (lc & 7)];
    }

    // h(0) = 0 for our slice, publish flag=1
    {
        uint2 z; z.x = 0u; z.y = 0u;
        g_hfrag[0][ng][wg][lane] = z;
    }
    __syncthreads();
    if (tid == 0) publish(ng, 1u);

    float c0 = 0.0f, c1 = 0.0f, c2 = 0.0f, c3 = 0.0f;
    const int g0 = ng & 3;   // staggered group start (the ONLY delta vs R4)

    for (int t = 0; t < TT; ++t) {
        const uint2* hb = &g_hfrag[t & 1][0][wg][lane];   // slice stride = 256 uint2
        const uint4* bf0 = Bf + lane;
        const uint4* bf1 = Bf + 2048 + lane;

        // Prefetch token indices for this step
        int vA = __ldg(&g_xidx[t * BB + R]);
        int vB = __ldg(&g_xidx[t * BB + R + 8]);

        float acc[4][4];
#pragma unroll
        for (int g = 0; g < 4; ++g)
#pragma unroll
            for (int e = 0; e < 4; ++e) acc[g][e] = 0.0f;

        const unsigned tgt = (unsigned)(t + 1);

        // 4 grouped waits, staggered start per CTA (R4 pipelining preserved:
        // every group is waited-on before use; order among groups arbitrary).
#pragma unroll 1
        for (int gi = 0; gi < 4; ++gi) {
            int grp = (g0 + gi) & 3;
            wait_group(grp, tgt);
#pragma unroll 8
            for (int ks = 16 * grp; ks < 16 * grp + 16; ++ks) {
                uint2 A01 = ldcg2(hb + (2 * ks) * 256);
                uint2 A23 = ldcg2(hb + (2 * ks + 1) * 256);
                uint4 B01 = bf0[ks * 32];
                uint4 B23 = bf1[ks * 32];
                mma_f16(acc[0], A01.x, A01.y, A23.x, A23.y, B01.x, B01.y);
                mma_f16(acc[1], A01.x, A01.y, A23.x, A23.y, B01.z, B01.w);
                mma_f16(acc[2], A01.x, A01.y, A23.x, A23.y, B23.x, B23.y);
                mma_f16(acc[3], A01.x, A01.y, A23.x, A23.y, B23.z, B23.w);
            }
        }

        // Gate math entirely in registers (C-fragment == gate-math element set)
        const float* xA = xzsm + vA * 33 + 2 * q;
        const float* xB = xzsm + vB * 33 + 2 * q;

        float h0 = lstm_elem(acc[0][0] + xA[0], acc[1][0] + xA[8],
                             acc[2][0] + xA[16], acc[3][0] + xA[24], c0);
        float h1 = lstm_elem(acc[0][1] + xA[1], acc[1][1] + xA[9],
                             acc[2][1] + xA[17], acc[3][1] + xA[25], c1);
        float h2 = lstm_elem(acc[0][2] + xB[0], acc[1][2] + xB[8],
                             acc[2][2] + xB[16], acc[3][2] + xB[24], c2);
        float h3 = lstm_elem(acc[0][3] + xB[1], acc[1][3] + xB[9],
                             acc[2][3] + xB[17], acc[3][3] + xB[25], c3);

        uint2 out;
        out.x = packh2(h0, h1);
        out.y = packh2(h2, h3);
        g_hfrag[(t + 1) & 1][ng][wg][lane] = out;

        // Publish h(t+1): all CTA stores ordered before the release store.
        __syncthreads();
        if (tid == 0) publish(ng, (unsigned)(t + 2));
    }
}

// ---------------------------------------------------------------------------
// Final projection + log_softmax; decodes fragment layout. h_final in buf 0.
__global__ void k_final(const float* __restrict__ W_ph, const float* __restrict__ b_p,
                        float* __restrict__ out) {
    __shared__ float part[CC][128];
    __shared__ float lg[CC];
    __shared__ float red[2];
    int b = blockIdx.x;
    int tid = threadIdx.x;
    int wg = b >> 4;
    int rr = b & 7;
    int e1 = (b >> 3) & 1;

    float loc[CC];
#pragma unroll
    for (int c = 0; c < CC; ++c) loc[c] = 0.0f;
    for (int col = tid; col < HH; col += 128) {
        int ns2 = col >> 3;
        int q = (col & 7) >> 1;
        int e0 = col & 1;
        uint2 ent = g_hfrag[0][ns2][wg][rr * 4 + q];
        unsigned word = e1 ? ent.y : ent.x;
        __half2 hh = *(__half2*)&word;
        float hv = e0 ? __high2float(hh) : __low2float(hh);
#pragma unroll
        for (int c = 0; c < CC; ++c) loc[c] += hv * W_ph[col * CC + c];
    }
#pragma unroll
    for (int c = 0; c < CC; ++c) part[c][tid] = loc[c];
    __syncthreads();
    if (tid < CC) {
        float s = 0.0f;
        for (int k = 0; k < 128; ++k) s += part[tid][k];
        lg[tid] = s + b_p[tid];
    }
    __syncthreads();
    if (tid == 0) {
        float m = -1e30f;
        for (int c = 0; c < CC; ++c) m = fmaxf(m, lg[c]);
        float s = 0.0f;
        for (int c = 0; c < CC; ++c) s += expf(lg[c] - m);
        red[0] = m;
        red[1] = logf(s);
    }
    __syncthreads();
    if (tid < CC) out[b * CC + tid] = lg[tid] - red[0] - red[1];
}

// ---------------------------------------------------------------------------
extern "C" void kernel_launch(void* const* d_in, const int* in_sizes, int n_in,
                              void* d_out, int out_size) {
    const void* x        = d_in[0];
    const float* emb     = (const float*)d_in[1];
    const float* W_gx    = (const float*)d_in[2];
    const float* W_ix    = (const float*)d_in[3];
    const float* W_fx    = (const float*)d_in[4];
    const float* W_ox    = (const float*)d_in[5];
    const float* W_gh    = (const float*)d_in[6];
    const float* W_ih    = (const float*)d_in[7];
    const float* W_fh    = (const float*)d_in[8];
    const float* W_oh    = (const float*)d_in[9];
    const float* b_g     = (const float*)d_in[10];
    const float* b_i     = (const float*)d_in[11];
    const float* b_f     = (const float*)d_in[12];
    const float* b_o     = (const float*)d_in[13];
    const float* W_ph    = (const float*)d_in[14];
    const float* b_p     = (const float*)d_in[15];
    float* out = (float*)d_out;

    cudaFuncSetAttribute(lstm_persistent, cudaFuncAttributeMaxDynamicSharedMemorySize,
                         SMEM_TOTAL);

    k_init<<<1, 128>>>();
    k_detect<<<1, 256>>>((const unsigned*)x);
    k_idx<<<BB, TT>>>(x);
    k_xz3<<<(VV * 4 * HH + 255) / 256, 256>>>(emb, W_gx, W_ix, W_fx, W_ox, b_g, b_i, b_f, b_o);
    lstm_persistent<<<GRID, NTHREADS, SMEM_TOTAL>>>(W_gh, W_ih, W_fh, W_oh);
    k_final<<<BB, 128>>>(W_ph, b_p, out);
}

// round 15
// speedup vs baseline: 1.2344x; 1.2344x over previous
#include <cuda_runtime.h>
#include <cuda_fp16.h>
#include <cstdint>

// Problem constants
#define BB 128      // batch
#define TT 256      // timesteps
#define DD 256      // embed dim
#define HH 1024     // hidden
#define CC 10       // classes
#define VV 3        // vocab
#define GRID 128    // persistent CTAs (1 per 8 h-cols)
#define NTHREADS 256
#define NWARP 8
#define KS16 64     // 1024 / 16 (K per m16n8k16 mma)

// SMEM: Bf uint4[2][64][32] = 64KB weight fragments (fp16), then xzsm[3][33]
#define SMEM_BF_BYTES (2 * 64 * 32 * 16)
#define SMEM_XZ_OFF   SMEM_BF_BYTES
#define SMEM_TOTAL    (SMEM_XZ_OFF + 3 * 33 * 4)

// h in A-fragment order, fp16, PAIRED for LDG.128 (R8-validated layout):
// g_hpack[buf][kp][wg][lane] = uint4 { slice(2kp) uint2 , slice(2kp+1) uint2 }
// slice s covers h-cols [8s, 8s+8) (owned by CTA s). For (wg, lane):
//   uint2 = { half2(h[R][c], h[R][c+1]), half2(h[R+8][c], h[R+8][c+1]) },
//   R = 16*wg + lane/4, c = 8*s + 2*(lane%4).
__device__ uint4 g_hpack[2][64][NWARP][32];
__device__ float g_xz3[VV * 4 * HH];   // per-token x-side projection [v][gate*1024+j]
__device__ int   g_xidx[TT * BB];      // token index, time-major
__device__ int   g_x64;
// Per-CTA data-flow flags (R4 scheme, UNCHANGED). g_flag[ng] = s means CTA ng
// has PUBLISHED h(s-1) (finished step s-2), hence also finished READING h(s-2).
// Consumer of step t needs flag >= t+1 per producer before consuming h(t).
// WAR safety: writer of h(t+1) (same buffer as h(t-1)) has seen all flags
// >= t+1, which implies every CTA finished reading h(t-1).
__device__ unsigned g_flag[GRID];

// ---------------------------------------------------------------------------
__device__ __forceinline__ unsigned packh2(float a, float b) {
    __half2 h = __floats2half2_rn(a, b);
    return *(unsigned*)&h;
}

__device__ __forceinline__ uint4 ldcg4(const uint4* p) {
    uint4 r;
    asm volatile("ld.global.cg.v4.u32 {%0,%1,%2,%3},[%4];"
                 : "=r"(r.x), "=r"(r.y), "=r"(r.z), "=r"(r.w) : "l"(p));
    return r;
}

__device__ __forceinline__ void mma_f16(float* c, unsigned a0, unsigned a1,
                                        unsigned a2, unsigned a3,
                                        unsigned b0, unsigned b1) {
    asm volatile(
        "mma.sync.aligned.m16n8k16.row.col.f32.f16.f16.f32 "
        "{%0,%1,%2,%3}, {%4,%5,%6,%7}, {%8,%9}, {%0,%1,%2,%3};"
        : "+f"(c[0]), "+f"(c[1]), "+f"(c[2]), "+f"(c[3])
        : "r"(a0), "r"(a1), "r"(a2), "r"(a3), "r"(b0), "r"(b1));
}

__device__ __forceinline__ float tanha(float x) {
    float y;
    asm("tanh.approx.f32 %0,%1;" : "=f"(y) : "f"(x));
    return y;
}

__device__ __forceinline__ float sigmf(float x) {
    float e = __expf(-x);
    float r;
    asm("rcp.approx.f32 %0,%1;" : "=f"(r) : "f"(1.0f + e));
    return r;
}

__device__ __forceinline__ float lstm_elem(float zg, float zi, float zf, float zo, float& c) {
    float gg = tanha(zg);
    float ii = sigmf(zi);
    float ff = sigmf(zf);
    float oo = sigmf(zo);
    c = c * ff + gg * ii;
    return tanha(c) * oo;
}

// Warp-collective: wait until producers [32g, 32g+32) have flag >= tgt.
__device__ __forceinline__ void wait_group(int g, unsigned tgt) {
    const unsigned* f = &g_flag[g * 32 + (threadIdx.x & 31)];
    unsigned v;
    do {
        asm volatile("ld.acquire.gpu.global.u32 %0,[%1];" : "=r"(v) : "l"(f) : "memory");
    } while (__any_sync(0xffffffffu, v < tgt));
}

__device__ __forceinline__ void publish(int ng, unsigned val) {
    asm volatile("st.release.gpu.global.u32 [%0],%1;"
                 :: "l"(&g_flag[ng]), "r"(val) : "memory");
}

// ---------------------------------------------------------------------------
__global__ void k_init() {
    int tid = threadIdx.x;
    if (tid < GRID) g_flag[tid] = 0u;
}

// Detect x dtype without reading past an int32-sized allocation.
__global__ void k_detect(const unsigned* __restrict__ xw) {
    __shared__ int flag;
    if (threadIdx.x == 0) flag = 0;
    __syncthreads();
    for (int i = threadIdx.x; i < 2048; i += blockDim.x)
        if (xw[2 * i + 1] != 0u) flag = 1;
    __syncthreads();
    if (threadIdx.x == 0) g_x64 = (flag == 0) ? 1 : 0;
}

__global__ void k_idx(const void* __restrict__ x) {
    int b = blockIdx.x;
    int t = threadIdx.x;
    long long v;
    if (g_x64) v = ((const long long*)x)[(size_t)b * TT + t];
    else       v = ((const int*)x)[(size_t)b * TT + t];
    g_xidx[t * BB + b] = (int)v;
}

__global__ void k_xz3(const float* __restrict__ emb,
                      const float* __restrict__ W_gx, const float* __restrict__ W_ix,
                      const float* __restrict__ W_fx, const float* __restrict__ W_ox,
                      const float* __restrict__ b_g, const float* __restrict__ b_i,
                      const float* __restrict__ b_f, const float* __restrict__ b_o) {
    int gid = blockIdx.x * blockDim.x + threadIdx.x;
    if (gid >= VV * 4 * HH) return;
    int v = gid >> 12;
    int col = gid & 4095;
    int gate = col >> 10;
    int j = col & 1023;
    const float* W = (gate == 0) ? W_gx : (gate == 1) ? W_ix : (gate == 2) ? W_fx : W_ox;
    const float* bb = (gate == 0) ? b_g : (gate == 1) ? b_i : (gate == 2) ? b_f : b_o;
    float s = bb[j];
    const float* ev = emb + v * DD;
#pragma unroll 8
    for (int d = 0; d < DD; ++d) s += ev[d] * W[d * HH + j];
    g_xz3[gid] = s;
}

// ---------------------------------------------------------------------------
// Persistent recurrent kernel: R4's EXACT schedule/sync (ascending grouped
// waits, block __syncthreads + lane-0 st.release publish) on the R8 paired
// h layout (64 x LDG.128 per warp per step instead of 128 x LDG.64).
// CTA ng owns h-cols [8ng, 8ng+8). Warp wg: rows [16wg,16wg+16), 32 z-cols.
__global__ void __launch_bounds__(NTHREADS, 1)
lstm_persistent(const float* __restrict__ W_gh, const float* __restrict__ W_ih,
                const float* __restrict__ W_fh, const float* __restrict__ W_oh) {
    extern __shared__ __align__(16) char smem[];
    uint4* Bf = (uint4*)smem;                     // [2][64][32]
    float* xzsm = (float*)(smem + SMEM_XZ_OFF);   // [3][33]

    const int ng = blockIdx.x;
    const int tid = threadIdx.x;
    const int wg = tid >> 5;
    const int lane = tid & 31;
    const int q = lane & 3;
    const int r4 = lane >> 2;
    const int R = 16 * wg + r4;

    // ---- One-time: weight slice -> fp16 B-fragments in SMEM ----
    for (int i = tid; i < 2 * KS16 * 32; i += NTHREADS) {
        int t = i & 31;
        int ks = (i >> 5) & 63;
        int p = i >> 11;                      // 0: gates g,i  1: gates f,o
        int col = ng * 8 + (t >> 2);
        int k0 = 16 * ks + 2 * (t & 3);
        const float* WA = p ? W_fh : W_gh;
        const float* WB = p ? W_oh : W_ih;
        uint4 v;
        v.x = packh2(WA[(size_t)k0 * HH + col],       WA[(size_t)(k0 + 1) * HH + col]);
        v.y = packh2(WA[(size_t)(k0 + 8) * HH + col], WA[(size_t)(k0 + 9) * HH + col]);
        v.z = packh2(WB[(size_t)k0 * HH + col],       WB[(size_t)(k0 + 1) * HH + col]);
        v.w = packh2(WB[(size_t)(k0 + 8) * HH + col], WB[(size_t)(k0 + 9) * HH + col]);
        Bf[i] = v;
    }

    // xz slice: xzsm[v][gate*8 + j] for this CTA's 8 cols
    for (int i = tid; i < VV * 32; i += NTHREADS) {
        int v = i >> 5;
        int lc = i & 31;
        xzsm[v * 33 + lc] = g_xz3[v * 4096 + (lc >> 3) * HH + ng * 8 + (lc & 7)];
    }

    // Producer write slot for this (ng, wg, lane): 8-byte half of a uint4.
    const int kp = ng >> 1;
    const int half = ng & 1;
    uint2* slot0 = (uint2*)((char*)&g_hpack[0][kp][wg][lane] + half * 8);
    uint2* slot1 = (uint2*)((char*)&g_hpack[1][kp][wg][lane] + half * 8);

    // h(0) = 0 for our fragment
    {
        uint2 z; z.x = 0u; z.y = 0u;
        *slot0 = z;
    }
    __syncthreads();
    if (tid == 0) publish(ng, 1u);

    float c0 = 0.0f, c1 = 0.0f, c2 = 0.0f, c3 = 0.0f;

    for (int t = 0; t < TT; ++t) {
        const uint4* hp = &g_hpack[t & 1][0][wg][lane];   // stride per kp = 256 uint4
        const uint4* bf0 = Bf + lane;
        const uint4* bf1 = Bf + 2048 + lane;

        // Prefetch token indices for this step
        int vA = __ldg(&g_xidx[t * BB + R]);
        int vB = __ldg(&g_xidx[t * BB + R + 8]);

        float acc[4][4];
#pragma unroll
        for (int g = 0; g < 4; ++g)
#pragma unroll
            for (int e = 0; e < 4; ++e) acc[g][e] = 0.0f;

        const unsigned tgt = (unsigned)(t + 1);

        // 4 grouped waits in ASCENDING k-order (R4-proven): group g covers
        // producers [32g,32g+32) = kp [16g,16g+16). Pipelines producer skew.
#pragma unroll 1
        for (int grp = 0; grp < 4; ++grp) {
            wait_group(grp, tgt);
#pragma unroll 8
            for (int ks = 16 * grp; ks < 16 * grp + 16; ++ks) {
                uint4 A = ldcg4(hp + ks * 256);   // A01 = .x/.y, A23 = .z/.w
                uint4 B01 = bf0[ks * 32];
                uint4 B23 = bf1[ks * 32];
                mma_f16(acc[0], A.x, A.y, A.z, A.w, B01.x, B01.y);
                mma_f16(acc[1], A.x, A.y, A.z, A.w, B01.z, B01.w);
                mma_f16(acc[2], A.x, A.y, A.z, A.w, B23.x, B23.y);
                mma_f16(acc[3], A.x, A.y, A.z, A.w, B23.z, B23.w);
            }
        }

        // Gate math entirely in registers (C-fragment == gate-math element set)
        const float* xA = xzsm + vA * 33 + 2 * q;
        const float* xB = xzsm + vB * 33 + 2 * q;

        float h0 = lstm_elem(acc[0][0] + xA[0], acc[1][0] + xA[8],
                             acc[2][0] + xA[16], acc[3][0] + xA[24], c0);
        float h1 = lstm_elem(acc[0][1] + xA[1], acc[1][1] + xA[9],
                             acc[2][1] + xA[17], acc[3][1] + xA[25], c1);
        float h2 = lstm_elem(acc[0][2] + xB[0], acc[1][2] + xB[8],
                             acc[2][2] + xB[16], acc[3][2] + xB[24], c2);
        float h3 = lstm_elem(acc[0][3] + xB[1], acc[1][3] + xB[9],
                             acc[2][3] + xB[17], acc[3][3] + xB[25], c3);

        uint2 out;
        out.x = packh2(h0, h1);
        out.y = packh2(h2, h3);
        *((t & 1) ? slot0 : slot1) = out;     // h(t+1) -> buffer (t+1)&1

        // Publish h(t+1): all CTA stores ordered before the release store
        // (R4's exact publish — NOT the R8 RED-atomic variant).
        __syncthreads();
        if (tid == 0) publish(ng, (unsigned)(t + 2));
    }
}

// ---------------------------------------------------------------------------
// Final projection + log_softmax; decodes packed fragment layout (buf 0).
__global__ void k_final(const float* __restrict__ W_ph, const float* __restrict__ b_p,
                        float* __restrict__ out) {
    __shared__ float part[CC][128];
    __shared__ float lg[CC];
    __shared__ float red[2];
    int b = blockIdx.x;
    int tid = threadIdx.x;
    int wg = b >> 4;
    int rr = b & 7;
    int e1 = (b >> 3) & 1;

    float loc[CC];
#pragma unroll
    for (int c = 0; c < CC; ++c) loc[c] = 0.0f;
    for (int col = tid; col < HH; col += 128) {
        int ns2 = col >> 3;        // 8-col slice
        int kp = ns2 >> 1;
        int half = ns2 & 1;
        int q = (col & 7) >> 1;
        int e0 = col & 1;
        uint4 ent = g_hpack[0][kp][wg][rr * 4 + q];
        unsigned word;
        if (half) word = e1 ? ent.w : ent.z;
        else      word = e1 ? ent.y : ent.x;
        __half2 hh = *(__half2*)&word;
        float hv = e0 ? __high2float(hh) : __low2float(hh);
#pragma unroll
        for (int c = 0; c < CC; ++c) loc[c] += hv * W_ph[col * CC + c];
    }
#pragma unroll
    for (int c = 0; c < CC; ++c) part[c][tid] = loc[c];
    __syncthreads();
    if (tid < CC) {
        float s = 0.0f;
        for (int k = 0; k < 128; ++k) s += part[tid][k];
        lg[tid] = s + b_p[tid];
    }
    __syncthreads();
    if (tid == 0) {
        float m = -1e30f;
        for (int c = 0; c < CC; ++c) m = fmaxf(m, lg[c]);
        float s = 0.0f;
        for (int c = 0; c < CC; ++c) s += expf(lg[c] - m);
        red[0] = m;
        red[1] = logf(s);
    }
    __syncthreads();
    if (tid < CC) out[b * CC + tid] = lg[tid] - red[0] - red[1];
}

// ---------------------------------------------------------------------------
extern "C" void kernel_launch(void* const* d_in, const int* in_sizes, int n_in,
                              void* d_out, int out_size) {
    const void* x        = d_in[0];
    const float* emb     = (const float*)d_in[1];
    const float* W_gx    = (const float*)d_in[2];
    const float* W_ix    = (const float*)d_in[3];
    const float* W_fx    = (const float*)d_in[4];
    const float* W_ox    = (const float*)d_in[5];
    const float* W_gh    = (const float*)d_in[6];
    const float* W_ih    = (const float*)d_in[7];
    const float* W_fh    = (const float*)d_in[8];
    const float* W_oh    = (const float*)d_in[9];
    const float* b_g     = (const float*)d_in[10];
    const float* b_i     = (const float*)d_in[11];
    const float* b_f     = (const float*)d_in[12];
    const float* b_o     = (const float*)d_in[13];
    const float* W_ph    = (const float*)d_in[14];
    const float* b_p     = (const float*)d_in[15];
    float* out = (float*)d_out;

    cudaFuncSetAttribute(lstm_persistent, cudaFuncAttributeMaxDynamicSharedMemorySize,
                         SMEM_TOTAL);

    k_init<<<1, 128>>>();
    k_detect<<<1, 256>>>((const unsigned*)x);
    k_idx<<<BB, TT>>>(x);
    k_xz3<<<(VV * 4 * HH + 255) / 256, 256>>>(emb, W_gx, W_ix, W_fx, W_ox, b_g, b_i, b_f, b_o);
    lstm_persistent<<<GRID, NTHREADS, SMEM_TOTAL>>>(W_gh, W_ih, W_fh, W_oh);
    k_final<<<BB, 128>>>(W_ph, b_p, out);
}

// round 16
// speedup vs baseline: 1.4298x; 1.1582x over previous
#include <cuda_runtime.h>
#include <cuda_fp16.h>
#include <cstdint>

// Problem constants
#define BB 128      // batch
#define TT 256      // timesteps
#define DD 256      // embed dim
#define HH 1024     // hidden
#define CC 10       // classes
#define VV 3        // vocab
#define GRID 128    // persistent CTAs (1 per 8 h-cols)
#define NTHREADS 256
#define KS16 64     // 1024 / 16 (K per m16n8k16 mma)

// SMEM: Bf uint4[2][64][32] = 64KB weight fragments (fp16), then xzsm[3][33]
#define SMEM_BF_BYTES (2 * 64 * 32 * 16)
#define SMEM_XZ_OFF   SMEM_BF_BYTES
#define SMEM_TOTAL    (SMEM_XZ_OFF + 3 * 33 * 4)

// h in A-fragment order, fp16 (R2-R4 proven layout — CHAMPION):
// g_hfrag[buf][s][rg][lane], lane=(r4=lane/4, q=lane%4):
//   .x = half2(h[16rg+r4][8s+2q],   h[16rg+r4][8s+2q+1])
//   .y = half2(h[16rg+8+r4][8s+2q], h[16rg+8+r4][8s+2q+1])
// slice s = h-cols [8s, 8s+8), owned by CTA s.
__device__ uint2 g_hfrag[2][128][8][32];
__device__ float g_xz3[VV * 4 * HH];   // per-token x-side projection [v][gate*1024+j]
__device__ int   g_xidx[TT * BB];      // token index, time-major
__device__ int   g_x64;
// Per-CTA data-flow flags (R4 scheme, UNCHANGED). g_flag[ng] = s means CTA ng
// has PUBLISHED h(s-1) (finished step s-2), hence also finished READING h(s-2).
// Consumer of step t needs flag >= t+1 per producer before consuming h(t).
// WAR safety: writer of h(t+1) (same buffer as h(t-1)) has seen all flags
// >= t+1, which implies every CTA finished reading h(t-1).
__device__ unsigned g_flag[GRID];

// ---------------------------------------------------------------------------
__device__ __forceinline__ unsigned packh2(float a, float b) {
    __half2 h = __floats2half2_rn(a, b);
    return *(unsigned*)&h;
}

__device__ __forceinline__ uint2 ldcg2(const uint2* p) {
    uint2 r;
    asm volatile("ld.global.cg.v2.u32 {%0,%1},[%2];" : "=r"(r.x), "=r"(r.y) : "l"(p));
    return r;
}

__device__ __forceinline__ void mma_f16(float* c, unsigned a0, unsigned a1,
                                        unsigned a2, unsigned a3,
                                        unsigned b0, unsigned b1) {
    asm volatile(
        "mma.sync.aligned.m16n8k16.row.col.f32.f16.f16.f32 "
        "{%0,%1,%2,%3}, {%4,%5,%6,%7}, {%8,%9}, {%0,%1,%2,%3};"
        : "+f"(c[0]), "+f"(c[1]), "+f"(c[2]), "+f"(c[3])
        : "r"(a0), "r"(a1), "r"(a2), "r"(a3), "r"(b0), "r"(b1));
}

__device__ __forceinline__ float tanha(float x) {
    float y;
    asm("tanh.approx.f32 %0,%1;" : "=f"(y) : "f"(x));
    return y;
}

__device__ __forceinline__ float sigmf(float x) {
    float e = __expf(-x);
    float r;
    asm("rcp.approx.f32 %0,%1;" : "=f"(r) : "f"(1.0f + e));
    return r;
}

__device__ __forceinline__ float lstm_elem(float zg, float zi, float zf, float zo, float& c) {
    float gg = tanha(zg);
    float ii = sigmf(zi);
    float ff = sigmf(zf);
    float oo = sigmf(zo);
    c = c * ff + gg * ii;
    return tanha(c) * oo;
}

// Warp-collective: wait until producers [32g, 32g+32) have flag >= tgt.
// R16 delta (the ONLY change vs the R4 champion): polite spin. First check
// is immediate (zero cost when already satisfied — steady-state groups 1-3);
// a failed check backs off 64ns before re-polling, cutting the L2 poll storm
// during the publish wave by >10x at <=64ns wakeup quantization cost.
__device__ __forceinline__ void wait_group(int g, unsigned tgt) {
    const unsigned* f = &g_flag[g * 32 + (threadIdx.x & 31)];
    unsigned v;
    asm volatile("ld.acquire.gpu.global.u32 %0,[%1];" : "=r"(v) : "l"(f) : "memory");
    while (__any_sync(0xffffffffu, v < tgt)) {
        __nanosleep(64);
        asm volatile("ld.acquire.gpu.global.u32 %0,[%1];" : "=r"(v) : "l"(f) : "memory");
    }
}

__device__ __forceinline__ void publish(int ng, unsigned val) {
    asm volatile("st.release.gpu.global.u32 [%0],%1;"
                 :: "l"(&g_flag[ng]), "r"(val) : "memory");
}

// ---------------------------------------------------------------------------
__global__ void k_init() {
    int tid = threadIdx.x;
    if (tid < GRID) g_flag[tid] = 0u;
}

// Detect x dtype without reading past an int32-sized allocation.
__global__ void k_detect(const unsigned* __restrict__ xw) {
    __shared__ int flag;
    if (threadIdx.x == 0) flag = 0;
    __syncthreads();
    for (int i = threadIdx.x; i < 2048; i += blockDim.x)
        if (xw[2 * i + 1] != 0u) flag = 1;
    __syncthreads();
    if (threadIdx.x == 0) g_x64 = (flag == 0) ? 1 : 0;
}

__global__ void k_idx(const void* __restrict__ x) {
    int b = blockIdx.x;
    int t = threadIdx.x;
    long long v;
    if (g_x64) v = ((const long long*)x)[(size_t)b * TT + t];
    else       v = ((const int*)x)[(size_t)b * TT + t];
    g_xidx[t * BB + b] = (int)v;
}

__global__ void k_xz3(const float* __restrict__ emb,
                      const float* __restrict__ W_gx, const float* __restrict__ W_ix,
                      const float* __restrict__ W_fx, const float* __restrict__ W_ox,
                      const float* __restrict__ b_g, const float* __restrict__ b_i,
                      const float* __restrict__ b_f, const float* __restrict__ b_o) {
    int gid = blockIdx.x * blockDim.x + threadIdx.x;
    if (gid >= VV * 4 * HH) return;
    int v = gid >> 12;
    int col = gid & 4095;
    int gate = col >> 10;
    int j = col & 1023;
    const float* W = (gate == 0) ? W_gx : (gate == 1) ? W_ix : (gate == 2) ? W_fx : W_ox;
    const float* bb = (gate == 0) ? b_g : (gate == 1) ? b_i : (gate == 2) ? b_f : b_o;
    float s = bb[j];
    const float* ev = emb + v * DD;
#pragma unroll 8
    for (int d = 0; d < DD; ++d) s += ev[d] * W[d * HH + j];
    g_xz3[gid] = s;
}

// ---------------------------------------------------------------------------
// Persistent recurrent kernel (R4 champion, verbatim). CTA ng owns h-cols
// [8ng, 8ng+8). Warp wg: batch rows [16wg, 16wg+16), all 32 z-cols
// (ntile = gate). c-state in registers; z never leaves the mma accumulators.
__global__ void __launch_bounds__(NTHREADS, 1)
lstm_persistent(const float* __restrict__ W_gh, const float* __restrict__ W_ih,
                const float* __restrict__ W_fh, const float* __restrict__ W_oh) {
    extern __shared__ __align__(16) char smem[];
    uint4* Bf = (uint4*)smem;                     // [2][64][32]
    float* xzsm = (float*)(smem + SMEM_XZ_OFF);   // [3][33]

    const int ng = blockIdx.x;
    const int tid = threadIdx.x;
    const int wg = tid >> 5;
    const int lane = tid & 31;
    const int q = lane & 3;
    const int r4 = lane >> 2;
    const int R = 16 * wg + r4;

    // ---- One-time: weight slice -> fp16 B-fragments in SMEM ----
    for (int i = tid; i < 2 * KS16 * 32; i += NTHREADS) {
        int t = i & 31;
        int ks = (i >> 5) & 63;
        int p = i >> 11;                      // 0: gates g,i  1: gates f,o
        int col = ng * 8 + (t >> 2);
        int k0 = 16 * ks + 2 * (t & 3);
        const float* WA = p ? W_fh : W_gh;
        const float* WB = p ? W_oh : W_ih;
        uint4 v;
        v.x = packh2(WA[(size_t)k0 * HH + col],       WA[(size_t)(k0 + 1) * HH + col]);
        v.y = packh2(WA[(size_t)(k0 + 8) * HH + col], WA[(size_t)(k0 + 9) * HH + col]);
        v.z = packh2(WB[(size_t)k0 * HH + col],       WB[(size_t)(k0 + 1) * HH + col]);
        v.w = packh2(WB[(size_t)(k0 + 8) * HH + col], WB[(size_t)(k0 + 9) * HH + col]);
        Bf[i] = v;
    }

    // xz slice: xzsm[v][gate*8 + j] for this CTA's 8 cols
    for (int i = tid; i < VV * 32; i += NTHREADS) {
        int v = i >> 5;
        int lc = i & 31;
        xzsm[v * 33 + lc] = g_xz3[v * 4096 + (lc >> 3) * HH + ng * 8 + (lc & 7)];
    }

    // h(0) = 0 for our slice, publish flag=1
    {
        uint2 z; z.x = 0u; z.y = 0u;
        g_hfrag[0][ng][wg][lane] = z;
    }
    __syncthreads();
    if (tid == 0) publish(ng, 1u);

    float c0 = 0.0f, c1 = 0.0f, c2 = 0.0f, c3 = 0.0f;

    for (int t = 0; t < TT; ++t) {
        const uint2* hb = &g_hfrag[t & 1][0][wg][lane];   // slice stride = 256 uint2
        const uint4* bf0 = Bf + lane;
        const uint4* bf1 = Bf + 2048 + lane;

        // Prefetch token indices for this step
        int vA = __ldg(&g_xidx[t * BB + R]);
        int vB = __ldg(&g_xidx[t * BB + R + 8]);

        float acc[4][4];
#pragma unroll
        for (int g = 0; g < 4; ++g)
#pragma unroll
            for (int e = 0; e < 4; ++e) acc[g][e] = 0.0f;

        const unsigned tgt = (unsigned)(t + 1);

        // 4 grouped waits in ascending k-order (R4-proven pipelining): group
        // g covers producers [32g,32g+32) = k-steps [16g,16g+16).
#pragma unroll 1
        for (int grp = 0; grp < 4; ++grp) {
            wait_group(grp, tgt);
#pragma unroll 8
            for (int ks = 16 * grp; ks < 16 * grp + 16; ++ks) {
                uint2 A01 = ldcg2(hb + (2 * ks) * 256);
                uint2 A23 = ldcg2(hb + (2 * ks + 1) * 256);
                uint4 B01 = bf0[ks * 32];
                uint4 B23 = bf1[ks * 32];
                mma_f16(acc[0], A01.x, A01.y, A23.x, A23.y, B01.x, B01.y);
                mma_f16(acc[1], A01.x, A01.y, A23.x, A23.y, B01.z, B01.w);
                mma_f16(acc[2], A01.x, A01.y, A23.x, A23.y, B23.x, B23.y);
                mma_f16(acc[3], A01.x, A01.y, A23.x, A23.y, B23.z, B23.w);
            }
        }

        // Gate math entirely in registers (C-fragment == gate-math element set)
        const float* xA = xzsm + vA * 33 + 2 * q;
        const float* xB = xzsm + vB * 33 + 2 * q;

        float h0 = lstm_elem(acc[0][0] + xA[0], acc[1][0] + xA[8],
                             acc[2][0] + xA[16], acc[3][0] + xA[24], c0);
        float h1 = lstm_elem(acc[0][1] + xA[1], acc[1][1] + xA[9],
                             acc[2][1] + xA[17], acc[3][1] + xA[25], c1);
        float h2 = lstm_elem(acc[0][2] + xB[0], acc[1][2] + xB[8],
                             acc[2][2] + xB[16], acc[3][2] + xB[24], c2);
        float h3 = lstm_elem(acc[0][3] + xB[1], acc[1][3] + xB[9],
                             acc[2][3] + xB[17], acc[3][3] + xB[25], c3);

        uint2 out;
        out.x = packh2(h0, h1);
        out.y = packh2(h2, h3);
        g_hfrag[(t + 1) & 1][ng][wg][lane] = out;

        // Publish h(t+1): all CTA stores ordered before the release store.
        __syncthreads();
        if (tid == 0) publish(ng, (unsigned)(t + 2));
    }
}

// ---------------------------------------------------------------------------
// Final projection + log_softmax; decodes fragment layout. h_final in buf 0.
__global__ void k_final(const float* __restrict__ W_ph, const float* __restrict__ b_p,
                        float* __restrict__ out) {
    __shared__ float part[CC][128];
    __shared__ float lg[CC];
    __shared__ float red[2];
    int b = blockIdx.x;
    int tid = threadIdx.x;
    int wg = b >> 4;
    int rr = b & 7;
    int e1 = (b >> 3) & 1;

    float loc[CC];
#pragma unroll
    for (int c = 0; c < CC; ++c) loc[c] = 0.0f;
    for (int col = tid; col < HH; col += 128) {
        int ns2 = col >> 3;
        int q = (col & 7) >> 1;
        int e0 = col & 1;
        uint2 ent = g_hfrag[0][ns2][wg][rr * 4 + q];
        unsigned word = e1 ? ent.y : ent.x;
        __half2 hh = *(__half2*)&word;
        float hv = e0 ? __high2float(hh) : __low2float(hh);
#pragma unroll
        for (int c = 0; c < CC; ++c) loc[c] += hv * W_ph[col * CC + c];
    }
#pragma unroll
    for (int c = 0; c < CC; ++c) part[c][tid] = loc[c];
    __syncthreads();
    if (tid < CC) {
        float s = 0.0f;
        for (int k = 0; k < 128; ++k) s += part[tid][k];
        lg[tid] = s + b_p[tid];
    }
    __syncthreads();
    if (tid == 0) {
        float m = -1e30f;
        for (int c = 0; c < CC; ++c) m = fmaxf(m, lg[c]);
        float s = 0.0f;
        for (int c = 0; c < CC; ++c) s += expf(lg[c] - m);
        red[0] = m;
        red[1] = logf(s);
    }
    __syncthreads();
    if (tid < CC) out[b * CC + tid] = lg[tid] - red[0] - red[1];
}

// ---------------------------------------------------------------------------
extern "C" void kernel_launch(void* const* d_in, const int* in_sizes, int n_in,
                              void* d_out, int out_size) {
    const void* x        = d_in[0];
    const float* emb     = (const float*)d_in[1];
    const float* W_gx    = (const float*)d_in[2];
    const float* W_ix    = (const float*)d_in[3];
    const float* W_fx    = (const float*)d_in[4];
    const float* W_ox    = (const float*)d_in[5];
    const float* W_gh    = (const float*)d_in[6];
    const float* W_ih    = (const float*)d_in[7];
    const float* W_fh    = (const float*)d_in[8];
    const float* W_oh    = (const float*)d_in[9];
    const float* b_g     = (const float*)d_in[10];
    const float* b_i     = (const float*)d_in[11];
    const float* b_f     = (const float*)d_in[12];
    const float* b_o     = (const float*)d_in[13];
    const float* W_ph    = (const float*)d_in[14];
    const float* b_p     = (const float*)d_in[15];
    float* out = (float*)d_out;

    cudaFuncSetAttribute(lstm_persistent, cudaFuncAttributeMaxDynamicSharedMemorySize,
                         SMEM_TOTAL);

    k_init<<<1, 128>>>();
    k_detect<<<1, 256>>>((const unsigned*)x);
    k_idx<<<BB, TT>>>(x);
    k_xz3<<<(VV * 4 * HH + 255) / 256, 256>>>(emb, W_gx, W_ix, W_fx, W_ox, b_g, b_i, b_f, b_o);
    lstm_persistent<<<GRID, NTHREADS, SMEM_TOTAL>>>(W_gh, W_ih, W_fh, W_oh);
    k_final<<<BB, 128>>>(W_ph, b_p, out);
}